// round 15
// baseline (speedup 1.0000x reference)
#include <cuda_runtime.h>
#include <cuda_bf16.h>
#include <math.h>
#include <float.h>
#include <stdint.h>

// Problem constants
#define BATCH    2
#define SEQ      2048
#define MTOK     (BATCH * SEQ)     // 4096 tokens
#define HID      4096
#define NHEADS   32
#define NKV      8
#define HDIM     128
#define KVHID    (NKV * HDIM)      // 1024
#define GK       4096              // K dim of every projection GEMM

#define LOG2E 1.4426950408889634f

// ---------------------------------------------------------------------------
// Scratch (allocation-free rule: device globals). uint4 for 16B alignment.
// ---------------------------------------------------------------------------
__device__ float g_q[(size_t)MTOK * HID];
__device__ float g_k[(size_t)MTOK * KVHID];

#define U4(nbf16) ((nbf16) / 8)
__device__ uint4 g_Xhi [U4((size_t)MTOK * HID)];
__device__ uint4 g_Xlo [U4((size_t)MTOK * HID)];
__device__ uint4 g_Wqhi[U4((size_t)HID * HID)];
__device__ uint4 g_Wqlo[U4((size_t)HID * HID)];
__device__ uint4 g_Wkhi[U4((size_t)KVHID * HID)];
__device__ uint4 g_Wklo[U4((size_t)KVHID * HID)];
__device__ uint4 g_Wvhi[U4((size_t)KVHID * HID)];
__device__ uint4 g_Wvlo[U4((size_t)KVHID * HID)];
__device__ uint4 g_Wohi[U4((size_t)HID * HID)];
__device__ uint4 g_Wolo[U4((size_t)HID * HID)];
__device__ uint4 g_Ahi [U4((size_t)MTOK * HID)];
__device__ uint4 g_Alo [U4((size_t)MTOK * HID)];
// flash bf16 operands
__device__ uint4 g_qhi [U4((size_t)MTOK * HID)];
__device__ uint4 g_qlo [U4((size_t)MTOK * HID)];
__device__ uint4 g_khi [U4((size_t)MTOK * KVHID)];
__device__ uint4 g_klo [U4((size_t)MTOK * KVHID)];
__device__ uint4 g_vhi [U4((size_t)MTOK * KVHID)];
__device__ uint4 g_vlo [U4((size_t)MTOK * KVHID)];

// ---------------------------------------------------------------------------
// Common helpers
// ---------------------------------------------------------------------------
__device__ __forceinline__ uint32_t swz(uint32_t off) {
    return off ^ ((off >> 3) & 0x70);
}
__device__ __forceinline__ uint32_t smem_u32(const void* p) {
    return (uint32_t)__cvta_generic_to_shared(p);
}
__device__ __forceinline__ void cp16(uint32_t dst, const void* src) {
    asm volatile("cp.async.cg.shared.global [%0], [%1], 16;\n" :: "r"(dst), "l"(src));
}
__device__ __forceinline__ void cp_commit() { asm volatile("cp.async.commit_group;\n"); }
__device__ __forceinline__ void cp_wait0() { asm volatile("cp.async.wait_group 0;\n"); }
__device__ __forceinline__ void cp_wait1() { asm volatile("cp.async.wait_group 1;\n"); }
__device__ __forceinline__ void ldsm4(uint32_t r[4], uint32_t addr) {
    asm volatile("ldmatrix.sync.aligned.m8n8.x4.shared.b16 {%0,%1,%2,%3}, [%4];\n"
        : "=r"(r[0]), "=r"(r[1]), "=r"(r[2]), "=r"(r[3]) : "r"(addr));
}
__device__ __forceinline__ void ldsm4t(uint32_t r[4], uint32_t addr) {
    asm volatile("ldmatrix.sync.aligned.m8n8.x4.trans.shared.b16 {%0,%1,%2,%3}, [%4];\n"
        : "=r"(r[0]), "=r"(r[1]), "=r"(r[2]), "=r"(r[3]) : "r"(addr));
}
__device__ __forceinline__ void mma16816(float c[4], const uint32_t a[4],
                                         uint32_t b0, uint32_t b1) {
    asm volatile(
        "mma.sync.aligned.m16n8k16.row.col.f32.bf16.bf16.f32 "
        "{%0,%1,%2,%3}, {%4,%5,%6,%7}, {%8,%9}, {%0,%1,%2,%3};\n"
        : "+f"(c[0]), "+f"(c[1]), "+f"(c[2]), "+f"(c[3])
        : "r"(a[0]), "r"(a[1]), "r"(a[2]), "r"(a[3]), "r"(b0), "r"(b1));
}
__device__ __forceinline__ void split2(float a, float b,
                                       __nv_bfloat162& h, __nv_bfloat162& l) {
    h = __floats2bfloat162_rn(a, b);
    l = __floats2bfloat162_rn(a - __bfloat162float(h.x), b - __bfloat162float(h.y));
}

// ---------------------------------------------------------------------------
// Split fp32 -> (bf16 hi, bf16 lo)
// ---------------------------------------------------------------------------
__global__ __launch_bounds__(256) void split_kernel(
    const float* __restrict__ src, __nv_bfloat16* __restrict__ hi,
    __nv_bfloat16* __restrict__ lo, int n4)
{
    int i = blockIdx.x * blockDim.x + threadIdx.x;
    if (i >= n4) return;
    float4 v = ((const float4*)src)[i];
    __nv_bfloat162 H01, H23, L01, L23;
    split2(v.x, v.y, H01, L01);
    split2(v.z, v.w, H23, L23);
    ((__nv_bfloat162*)hi)[2 * i]     = H01;
    ((__nv_bfloat162*)hi)[2 * i + 1] = H23;
    ((__nv_bfloat162*)lo)[2 * i]     = L01;
    ((__nv_bfloat162*)lo)[2 * i + 1] = L23;
}

// ---------------------------------------------------------------------------
// bf16x3 mma.sync GEMM body: C tile 128x128, R15 config:
// 4 warps (wm = wid>>1, wn = wid&1), warp tile 64x64, 128 threads.
// mma:ldsm = 32:8 per kk16 (was 16:6) — 4x ILP per fragment load,
// half the barrier participants. 3-stage cp.async, 96KB -> 2 CTAs/SM
// (256 thr/SM => 256-reg budget: 128 acc + 32 frag + addr ~ 190, no spill).
// Warp-tile fragment/epilogue mapping identical to the R7/R9-verified code.
// ---------------------------------------------------------------------------
#define G_STAGES 3
#define G_TILE   (128 * 64 * 2)               // 16KB per operand tile
#define G_SMEM   (G_STAGES * 2 * G_TILE)      // 96KB
#define G_KCHUNKS (3 * GK / 64)               // 192

__device__ __forceinline__ void gemm_body_128x128(
    const __nv_bfloat16* __restrict__ Ahi, const __nv_bfloat16* __restrict__ Alo,
    const __nv_bfloat16* __restrict__ Bhi, const __nv_bfloat16* __restrict__ Blo,
    float* __restrict__ Cf, __nv_bfloat16* __restrict__ Chi,
    __nv_bfloat16* __restrict__ Clo,
    int ldC, int bm, int bn, char* dsm)
{
    const uint32_t aS = smem_u32(dsm);
    const uint32_t bS = aS + G_STAGES * G_TILE;

    const int tid  = threadIdx.x;
    const int lane = tid & 31;
    const int wid  = tid >> 5;
    const int wm   = wid >> 1;          // 0..1 -> 64-row slice
    const int wn   = wid & 1;           // 0..1 -> 64-col slice

    float acc[4][8][4];
#pragma unroll
    for (int i = 0; i < 4; i++)
#pragma unroll
        for (int j = 0; j < 8; j++)
#pragma unroll
            for (int t = 0; t < 4; t++) acc[i][j][t] = 0.f;

    // per-thread load indices: A 1024 16B units + B 1024 units over 128 thr
    int lr[8], lj[8];
#pragma unroll
    for (int i = 0; i < 8; i++) {
        int lin = i * 128 + tid;
        lr[i] = lin >> 3;
        lj[i] = lin & 7;
    }

    auto issue_loads = [&](int c, int st) {
        int pass  = c >> 6;
        int kreal = (c & 63) << 6;
        const __nv_bfloat16* Asrc = (pass < 2) ? Ahi : Alo;
        const __nv_bfloat16* Bsrc = (pass == 1) ? Blo : Bhi;
#pragma unroll
        for (int i = 0; i < 8; i++) {
            uint32_t off = swz(lr[i] * 128 + lj[i] * 16);
            cp16(aS + st * G_TILE + off,
                 Asrc + (size_t)(bm + lr[i]) * GK + kreal + lj[i] * 8);
            cp16(bS + st * G_TILE + off,
                 Bsrc + (size_t)(bn + lr[i]) * GK + kreal + lj[i] * 8);
        }
    };

    issue_loads(0, 0); cp_commit();
    issue_loads(1, 1); cp_commit();

    for (int c = 0; c < G_KCHUNKS; c++) {
        cp_wait1();
        __syncthreads();

        if (c + 2 < G_KCHUNKS) issue_loads(c + 2, (c + 2) % G_STAGES);
        cp_commit();

        const int st = c % G_STAGES;
        const uint32_t aT = aS + st * G_TILE;
        const uint32_t bT = bS + st * G_TILE;

#pragma unroll
        for (int kk = 0; kk < 64; kk += 16) {
            uint32_t afr[4][4];
            uint32_t bfr[4][4];
#pragma unroll
            for (int mt = 0; mt < 4; mt++) {
                int row = wm * 64 + mt * 16 + (lane & 15);
                uint32_t off = row * 128 + kk * 2 + (lane >> 4) * 16;
                ldsm4(afr[mt], aT + swz(off));
            }
#pragma unroll
            for (int nt2 = 0; nt2 < 4; nt2++) {
                int row = wn * 64 + nt2 * 16 + (lane & 7) + ((lane >> 4) & 1) * 8;
                uint32_t off = row * 128 + kk * 2 + ((lane >> 3) & 1) * 16;
                ldsm4(bfr[nt2], bT + swz(off));
            }
#pragma unroll
            for (int mt = 0; mt < 4; mt++)
#pragma unroll
                for (int nt = 0; nt < 8; nt++)
                    mma16816(acc[mt][nt], afr[mt],
                             bfr[nt >> 1][(nt & 1) * 2],
                             bfr[nt >> 1][(nt & 1) * 2 + 1]);
        }
    }

    // epilogue (R7/R9-verified mapping): fp32 or bf16 hi/lo split
#pragma unroll
    for (int mt = 0; mt < 4; mt++) {
#pragma unroll
        for (int nt = 0; nt < 8; nt++) {
            int row = bm + wm * 64 + mt * 16 + (lane >> 2);
            int col = bn + wn * 64 + nt * 8 + (lane & 3) * 2;
            if (Cf) {
                *(float2*)&Cf[(size_t)row * ldC + col] =
                    make_float2(acc[mt][nt][0], acc[mt][nt][1]);
                *(float2*)&Cf[(size_t)(row + 8) * ldC + col] =
                    make_float2(acc[mt][nt][2], acc[mt][nt][3]);
            } else {
                __nv_bfloat162 h0, l0, h1, l1;
                split2(acc[mt][nt][0], acc[mt][nt][1], h0, l0);
                split2(acc[mt][nt][2], acc[mt][nt][3], h1, l1);
                *(__nv_bfloat162*)&Chi[(size_t)row * ldC + col] = h0;
                *(__nv_bfloat162*)&Clo[(size_t)row * ldC + col] = l0;
                *(__nv_bfloat162*)&Chi[(size_t)(row + 8) * ldC + col] = h1;
                *(__nv_bfloat162*)&Clo[(size_t)(row + 8) * ldC + col] = l1;
            }
        }
    }
}

// Fused QKV projection: virtual N = 6144 (Wq 4096 | Wk 1024 | Wv 1024).
__global__ __launch_bounds__(128, 2) void gemm_qkv(
    const __nv_bfloat16* __restrict__ Xhi, const __nv_bfloat16* __restrict__ Xlo,
    const __nv_bfloat16* __restrict__ Wqhi, const __nv_bfloat16* __restrict__ Wqlo,
    const __nv_bfloat16* __restrict__ Wkhi, const __nv_bfloat16* __restrict__ Wklo,
    const __nv_bfloat16* __restrict__ Wvhi, const __nv_bfloat16* __restrict__ Wvlo,
    float* __restrict__ q, float* __restrict__ k,
    __nv_bfloat16* __restrict__ vhi, __nv_bfloat16* __restrict__ vlo)
{
    extern __shared__ __align__(16) char dsm[];
    const int bm = blockIdx.y * 128;
    const int bnG = blockIdx.x * 128;

    if (bnG < HID) {
        gemm_body_128x128(Xhi, Xlo, Wqhi, Wqlo, q, nullptr, nullptr,
                          HID, bm, bnG, dsm);
    } else if (bnG < HID + KVHID) {
        gemm_body_128x128(Xhi, Xlo, Wkhi, Wklo, k, nullptr, nullptr,
                          KVHID, bm, bnG - HID, dsm);
    } else {
        gemm_body_128x128(Xhi, Xlo, Wvhi, Wvlo, nullptr, vhi, vlo,
                          KVHID, bm, bnG - HID - KVHID, dsm);
    }
}

// O projection: bf16x3 inputs -> fp32 out
__global__ __launch_bounds__(128, 2) void gemm_nt(
    const __nv_bfloat16* __restrict__ Ahi, const __nv_bfloat16* __restrict__ Alo,
    const __nv_bfloat16* __restrict__ Bhi, const __nv_bfloat16* __restrict__ Blo,
    float* __restrict__ C, int N)
{
    extern __shared__ __align__(16) char dsm[];
    gemm_body_128x128(Ahi, Alo, Bhi, Blo, C, nullptr, nullptr,
                      N, blockIdx.y * 128, blockIdx.x * 128, dsm);
}

// ---------------------------------------------------------------------------
// RoPE + split: q (scaled by 1/sqrt(d)) and k -> bf16 hi/lo pairs.
// ---------------------------------------------------------------------------
__global__ __launch_bounds__(256) void rope_split_kernel(
    const float* __restrict__ Qb, const float* __restrict__ Kb,
    __nv_bfloat16* __restrict__ qhi, __nv_bfloat16* __restrict__ qlo,
    __nv_bfloat16* __restrict__ khi, __nv_bfloat16* __restrict__ klo,
    const int* __restrict__ pos)
{
    int idx = blockIdx.x * blockDim.x + threadIdx.x;   // MTOK*64
    int token = idx >> 6;
    int j = idx & 63;
    double inv = exp(((double)(-2 * j) / 128.0) * log(10000.0));
    double ang = (double)pos[token] * inv;
    float c = (float)cos(ang);
    float s = (float)sin(ang);
    const float scale = 0.08838834764831845f;

    auto wr = [](__nv_bfloat16* hi, __nv_bfloat16* lo, size_t off, float y) {
        __nv_bfloat16 h = __float2bfloat16(y);
        hi[off] = h;
        lo[off] = __float2bfloat16(y - __bfloat162float(h));
    };

    const float* q = Qb + (size_t)token * HID;
    size_t qo = (size_t)token * HID;
#pragma unroll
    for (int h = 0; h < NHEADS; h++) {
        float x1 = q[h * HDIM + j];
        float x2 = q[h * HDIM + 64 + j];
        wr(qhi, qlo, qo + h * HDIM + j,      (x1 * c - x2 * s) * scale);
        wr(qhi, qlo, qo + h * HDIM + 64 + j, (x2 * c + x1 * s) * scale);
    }
    const float* k = Kb + (size_t)token * KVHID;
    size_t ko = (size_t)token * KVHID;
#pragma unroll
    for (int h = 0; h < NKV; h++) {
        float x1 = k[h * HDIM + j];
        float x2 = k[h * HDIM + 64 + j];
        wr(khi, klo, ko + h * HDIM + j,      x1 * c - x2 * s);
        wr(khi, klo, ko + h * HDIM + 64 + j, x2 * c + x1 * s);
    }
}

// ---------------------------------------------------------------------------
// Tensor-core flash attention (R14-verified: pass-merged fragment reuse,
// qt reversed, bf16 split epilogue). UNCHANGED this round.
// ---------------------------------------------------------------------------
#define FQ  128
#define FKV 64
#define FLASH_SMEM (192 * 1024)

__global__ __launch_bounds__(256, 1) void flash_mma(
    const __nv_bfloat16* __restrict__ Qhi, const __nv_bfloat16* __restrict__ Qlo,
    const __nv_bfloat16* __restrict__ Khi, const __nv_bfloat16* __restrict__ Klo,
    const __nv_bfloat16* __restrict__ Vhi, const __nv_bfloat16* __restrict__ Vlo,
    __nv_bfloat16* __restrict__ Ohi, __nv_bfloat16* __restrict__ Olo)
{
    extern __shared__ __align__(16) char fsm[];
    const uint32_t smBase = smem_u32(fsm);

    const int tid = threadIdx.x, lane = tid & 31, wid = tid >> 5;
    const int qt = gridDim.x - 1 - blockIdx.x;   // heavy q-tiles first
    const int h = blockIdx.y, b = blockIdx.z;
    const int q0 = qt * FQ;
    const int kvh = h >> 2;
    const int ntiles = (q0 + FQ) / FKV;
    const int rowbase = wid * 16;

    {
        const __nv_bfloat16* qs[2] = {
            Qhi + ((size_t)b * SEQ + q0) * HID + h * HDIM,
            Qlo + ((size_t)b * SEQ + q0) * HID + h * HDIM };
#pragma unroll
        for (int t = 0; t < 2; t++)
#pragma unroll
            for (int i = 0; i < 8; i++) {
                int u = tid + 256 * i;
                int row = u >> 4, j = u & 15;
                cp16(smBase + t * 32768 + (j >> 3) * 16384 + swz(row * 128 + (j & 7) * 16),
                     qs[t] + (size_t)row * HID + j * 8);
            }
        cp_commit();
    }

    auto issue_kv = [&](int kt, int s) {
        const int k0 = kt * FKV;
        const size_t base = ((size_t)b * SEQ + k0) * KVHID + kvh * HDIM;
        const __nv_bfloat16* srcs[4] = { Khi + base, Klo + base, Vhi + base, Vlo + base };
        const uint32_t dbase = smBase + 65536 + s * 65536;
#pragma unroll
        for (int bfi = 0; bfi < 4; bfi++)
#pragma unroll
            for (int i = 0; i < 4; i++) {
                int u = tid + 256 * i;
                int row = u >> 4, j = u & 15;
                cp16(dbase + bfi * 16384 + (j >> 3) * 8192 + swz(row * 128 + (j & 7) * 16),
                     srcs[bfi] + (size_t)row * KVHID + j * 8);
            }
    };

    issue_kv(0, 0); cp_commit();

    float m0 = -1e30f, m1 = -1e30f, l0 = 0.f, l1 = 0.f;
    float oacc[16][4];
#pragma unroll
    for (int i = 0; i < 16; i++)
#pragma unroll
        for (int j = 0; j < 4; j++) oacc[i][j] = 0.f;

    for (int kt = 0; kt < ntiles; kt++) {
        if (kt + 1 < ntiles) { issue_kv(kt + 1, (kt + 1) & 1); cp_commit(); cp_wait1(); }
        else                 { cp_wait0(); }
        __syncthreads();

        const int k0 = kt * FKV;
        const bool active = (k0 <= q0 + rowbase + 15);
        if (active) {
            const uint32_t kvb = smBase + 65536 + (kt & 1) * 65536;
            const uint32_t khiS = kvb, kloS = kvb + 16384;
            const uint32_t vhiS = kvb + 32768, vloS = kvb + 49152;

            float sacc[8][4];
#pragma unroll
            for (int i = 0; i < 8; i++)
#pragma unroll
                for (int j = 0; j < 4; j++) sacc[i][j] = 0.f;

            // ---- S = QK^T, pass-merged ----
#pragma unroll
            for (int kk = 0; kk < 128; kk += 16) {
                uint32_t afh[4], afl[4];
                {
                    int row = rowbase + (lane & 15);
                    uint32_t off = (kk >> 6) * 16384 +
                        swz(row * 128 + (kk & 63) * 2 + (lane >> 4) * 16);
                    ldsm4(afh, smBase + off);            // Qhi
                    ldsm4(afl, smBase + 32768 + off);    // Qlo
                }
                uint32_t bf[4][4];
                uint32_t boff[4];
#pragma unroll
                for (int nt2 = 0; nt2 < 4; nt2++) {
                    int row = nt2 * 16 + (lane & 7) + ((lane >> 4) & 1) * 8;
                    boff[nt2] = (kk >> 6) * 8192 +
                        swz(row * 128 + (kk & 63) * 2 + ((lane >> 3) & 1) * 16);
                    ldsm4(bf[nt2], khiS + boff[nt2]);    // khi
                }
#pragma unroll
                for (int nt = 0; nt < 8; nt++)           // qhi*khi
                    mma16816(sacc[nt], afh,
                             bf[nt >> 1][(nt & 1) * 2],
                             bf[nt >> 1][(nt & 1) * 2 + 1]);
#pragma unroll
                for (int nt = 0; nt < 8; nt++)           // qlo*khi
                    mma16816(sacc[nt], afl,
                             bf[nt >> 1][(nt & 1) * 2],
                             bf[nt >> 1][(nt & 1) * 2 + 1]);
#pragma unroll
                for (int nt2 = 0; nt2 < 4; nt2++)
                    ldsm4(bf[nt2], kloS + boff[nt2]);    // klo
#pragma unroll
                for (int nt = 0; nt < 8; nt++)           // qhi*klo
                    mma16816(sacc[nt], afh,
                             bf[nt >> 1][(nt & 1) * 2],
                             bf[nt >> 1][(nt & 1) * 2 + 1]);
            }

            const int rg0 = q0 + rowbase + (lane >> 2);
            if (k0 + 63 > q0 + rowbase) {
#pragma unroll
                for (int nt = 0; nt < 8; nt++) {
                    int cbase = k0 + nt * 8 + (lane & 3) * 2;
                    if (cbase     > rg0)     sacc[nt][0] = -1e30f;
                    if (cbase + 1 > rg0)     sacc[nt][1] = -1e30f;
                    if (cbase     > rg0 + 8) sacc[nt][2] = -1e30f;
                    if (cbase + 1 > rg0 + 8) sacc[nt][3] = -1e30f;
                }
            }

            float mx0 = m0, mx1 = m1;
#pragma unroll
            for (int nt = 0; nt < 8; nt++) {
                mx0 = fmaxf(mx0, fmaxf(sacc[nt][0], sacc[nt][1]));
                mx1 = fmaxf(mx1, fmaxf(sacc[nt][2], sacc[nt][3]));
            }
            mx0 = fmaxf(mx0, __shfl_xor_sync(0xffffffff, mx0, 1));
            mx0 = fmaxf(mx0, __shfl_xor_sync(0xffffffff, mx0, 2));
            mx1 = fmaxf(mx1, __shfl_xor_sync(0xffffffff, mx1, 1));
            mx1 = fmaxf(mx1, __shfl_xor_sync(0xffffffff, mx1, 2));

            const float f0 = exp2f((m0 - mx0) * LOG2E);
            const float f1 = exp2f((m1 - mx1) * LOG2E);
            m0 = mx0; m1 = mx1;

            uint32_t pahi[4][4], palo[4][4];
            float l0a = 0.f, l1a = 0.f;
#pragma unroll
            for (int nt = 0; nt < 8; nt++) {
                float p0 = exp2f((sacc[nt][0] - mx0) * LOG2E);
                float p1 = exp2f((sacc[nt][1] - mx0) * LOG2E);
                float p2 = exp2f((sacc[nt][2] - mx1) * LOG2E);
                float p3 = exp2f((sacc[nt][3] - mx1) * LOG2E);
                l0a += p0 + p1; l1a += p2 + p3;
                int kt2 = nt >> 1, odd = nt & 1;
                __nv_bfloat162 h01, lo01, h23, lo23;
                split2(p0, p1, h01, lo01);
                split2(p2, p3, h23, lo23);
                pahi[kt2][odd * 2]     = *(uint32_t*)&h01;
                pahi[kt2][odd * 2 + 1] = *(uint32_t*)&h23;
                palo[kt2][odd * 2]     = *(uint32_t*)&lo01;
                palo[kt2][odd * 2 + 1] = *(uint32_t*)&lo23;
            }
            l0a += __shfl_xor_sync(0xffffffff, l0a, 1);
            l0a += __shfl_xor_sync(0xffffffff, l0a, 2);
            l1a += __shfl_xor_sync(0xffffffff, l1a, 1);
            l1a += __shfl_xor_sync(0xffffffff, l1a, 2);
            l0 = l0 * f0 + l0a;
            l1 = l1 * f1 + l1a;

#pragma unroll
            for (int nt = 0; nt < 16; nt++) {
                oacc[nt][0] *= f0; oacc[nt][1] *= f0;
                oacc[nt][2] *= f1; oacc[nt][3] *= f1;
            }

            // ---- O += P V, pass-merged ----
#pragma unroll
            for (int kt2 = 0; kt2 < 4; kt2++) {
#pragma unroll
                for (int nt16 = 0; nt16 < 8; nt16++) {
                    uint32_t vf[4];
                    int kv = kt2 * 16 + (lane & 15);
                    int d  = nt16 * 16 + (lane >> 4) * 8;
                    uint32_t off = (d >> 6) * 8192 + swz(kv * 128 + (d & 63) * 2);
                    ldsm4t(vf, vhiS + off);              // vhi
                    mma16816(oacc[nt16 * 2],     pahi[kt2], vf[0], vf[1]);
                    mma16816(oacc[nt16 * 2 + 1], pahi[kt2], vf[2], vf[3]);
                    mma16816(oacc[nt16 * 2],     palo[kt2], vf[0], vf[1]);
                    mma16816(oacc[nt16 * 2 + 1], palo[kt2], vf[2], vf[3]);
                    ldsm4t(vf, vloS + off);              // vlo
                    mma16816(oacc[nt16 * 2],     pahi[kt2], vf[0], vf[1]);
                    mma16816(oacc[nt16 * 2 + 1], pahi[kt2], vf[2], vf[3]);
                }
            }
        }
        __syncthreads();
    }

    // epilogue: normalize + bf16 hi/lo split store
    const float il0 = 1.f / l0, il1 = 1.f / l1;
    const size_t obase = ((size_t)b * SEQ + q0 + rowbase + (lane >> 2)) * HID + h * HDIM;
#pragma unroll
    for (int nt = 0; nt < 16; nt++) {
        int d = nt * 8 + (lane & 3) * 2;
        __nv_bfloat162 h0, lo0, h1, lo1;
        split2(oacc[nt][0] * il0, oacc[nt][1] * il0, h0, lo0);
        split2(oacc[nt][2] * il1, oacc[nt][3] * il1, h1, lo1);
        *(__nv_bfloat162*)&Ohi[obase + d]           = h0;
        *(__nv_bfloat162*)&Olo[obase + d]           = lo0;
        *(__nv_bfloat162*)&Ohi[obase + 8 * HID + d] = h1;
        *(__nv_bfloat162*)&Olo[obase + 8 * HID + d] = lo1;
    }
}

// ---------------------------------------------------------------------------
// Launch
// ---------------------------------------------------------------------------
extern "C" void kernel_launch(void* const* d_in, const int* in_sizes, int n_in,
                              void* d_out, int out_size)
{
    const float* X   = (const float*)d_in[0];
    const int*   pos = (const int*)d_in[1];
    const float* Wq  = (const float*)d_in[2];
    const float* Wk  = (const float*)d_in[3];
    const float* Wv  = (const float*)d_in[4];
    const float* Wo  = (const float*)d_in[5];
    float* out = (float*)d_out;

    float *q, *k;
    cudaGetSymbolAddress((void**)&q, g_q);
    cudaGetSymbolAddress((void**)&k, g_k);

    __nv_bfloat16 *Xhi, *Xlo, *Wqhi, *Wqlo, *Wkhi, *Wklo, *Wvhi, *Wvlo, *Wohi, *Wolo, *Ahi, *Alo;
    __nv_bfloat16 *qhi, *qlo, *khi, *klo, *vhi, *vlo;
    cudaGetSymbolAddress((void**)&Xhi,  g_Xhi);  cudaGetSymbolAddress((void**)&Xlo,  g_Xlo);
    cudaGetSymbolAddress((void**)&Wqhi, g_Wqhi); cudaGetSymbolAddress((void**)&Wqlo, g_Wqlo);
    cudaGetSymbolAddress((void**)&Wkhi, g_Wkhi); cudaGetSymbolAddress((void**)&Wklo, g_Wklo);
    cudaGetSymbolAddress((void**)&Wvhi, g_Wvhi); cudaGetSymbolAddress((void**)&Wvlo, g_Wvlo);
    cudaGetSymbolAddress((void**)&Wohi, g_Wohi); cudaGetSymbolAddress((void**)&Wolo, g_Wolo);
    cudaGetSymbolAddress((void**)&Ahi,  g_Ahi);  cudaGetSymbolAddress((void**)&Alo,  g_Alo);
    cudaGetSymbolAddress((void**)&qhi,  g_qhi);  cudaGetSymbolAddress((void**)&qlo,  g_qlo);
    cudaGetSymbolAddress((void**)&khi,  g_khi);  cudaGetSymbolAddress((void**)&klo,  g_klo);
    cudaGetSymbolAddress((void**)&vhi,  g_vhi);  cudaGetSymbolAddress((void**)&vlo,  g_vlo);

    const int n16M = MTOK * HID / 4;
    const int n16W = HID * HID / 4;
    const int n4W  = KVHID * HID / 4;

    // Splits of inputs
    split_kernel<<<(n16M + 255) / 256, 256>>>(X,  Xhi,  Xlo,  n16M);
    split_kernel<<<(n16W + 255) / 256, 256>>>(Wq, Wqhi, Wqlo, n16W);
    split_kernel<<<(n4W  + 255) / 256, 256>>>(Wk, Wkhi, Wklo, n4W);
    split_kernel<<<(n4W  + 255) / 256, 256>>>(Wv, Wvhi, Wvlo, n4W);
    split_kernel<<<(n16W + 255) / 256, 256>>>(Wo, Wohi, Wolo, n16W);

    // Fused QKV projection (virtual N = 6144; V epilogue writes bf16 split)
    cudaFuncSetAttribute(gemm_qkv, cudaFuncAttributeMaxDynamicSharedMemorySize, G_SMEM);
    cudaFuncSetAttribute(gemm_nt,  cudaFuncAttributeMaxDynamicSharedMemorySize, G_SMEM);
    gemm_qkv<<<dim3((HID + 2 * KVHID) / 128, MTOK / 128), 128, G_SMEM>>>(
        Xhi, Xlo, Wqhi, Wqlo, Wkhi, Wklo, Wvhi, Wvlo, q, k, vhi, vlo);

    // RoPE (+scale) and split for flash operands
    rope_split_kernel<<<(MTOK * 64) / 256, 256>>>(q, k, qhi, qlo, khi, klo, pos);

    // Tensor-core flash attention (epilogue writes bf16 split directly)
    cudaFuncSetAttribute(flash_mma, cudaFuncAttributeMaxDynamicSharedMemorySize, FLASH_SMEM);
    flash_mma<<<dim3(SEQ / FQ, NHEADS, BATCH), 256, FLASH_SMEM>>>(
        qhi, qlo, khi, klo, vhi, vlo, Ahi, Alo);

    // Output projection
    gemm_nt<<<dim3(HID / 128, MTOK / 128), 128, G_SMEM>>>(Ahi, Alo, Wohi, Wolo, out, HID);
}

// round 16
// speedup vs baseline: 1.0755x; 1.0755x over previous
#include <cuda_runtime.h>
#include <cuda_bf16.h>
#include <math.h>
#include <float.h>
#include <stdint.h>

// Problem constants
#define BATCH    2
#define SEQ      2048
#define MTOK     (BATCH * SEQ)     // 4096 tokens
#define HID      4096
#define NHEADS   32
#define NKV      8
#define HDIM     128
#define KVHID    (NKV * HDIM)      // 1024
#define GK       4096              // K dim of every projection GEMM

#define LOG2E 1.4426950408889634f

// ---------------------------------------------------------------------------
// Scratch (allocation-free rule: device globals). uint4 for 16B alignment.
// ---------------------------------------------------------------------------
__device__ float g_q[(size_t)MTOK * HID];
__device__ float g_k[(size_t)MTOK * KVHID];

#define U4(nbf16) ((nbf16) / 8)
__device__ uint4 g_Xhi [U4((size_t)MTOK * HID)];
__device__ uint4 g_Xlo [U4((size_t)MTOK * HID)];
__device__ uint4 g_Wqhi[U4((size_t)HID * HID)];
__device__ uint4 g_Wqlo[U4((size_t)HID * HID)];
__device__ uint4 g_Wkhi[U4((size_t)KVHID * HID)];
__device__ uint4 g_Wklo[U4((size_t)KVHID * HID)];
__device__ uint4 g_Wvhi[U4((size_t)KVHID * HID)];
__device__ uint4 g_Wvlo[U4((size_t)KVHID * HID)];
__device__ uint4 g_Wohi[U4((size_t)HID * HID)];
__device__ uint4 g_Wolo[U4((size_t)HID * HID)];
__device__ uint4 g_Ahi [U4((size_t)MTOK * HID)];
__device__ uint4 g_Alo [U4((size_t)MTOK * HID)];
// flash bf16 operands
__device__ uint4 g_qhi [U4((size_t)MTOK * HID)];
__device__ uint4 g_qlo [U4((size_t)MTOK * HID)];
__device__ uint4 g_khi [U4((size_t)MTOK * KVHID)];
__device__ uint4 g_klo [U4((size_t)MTOK * KVHID)];
__device__ uint4 g_vhi [U4((size_t)MTOK * KVHID)];
__device__ uint4 g_vlo [U4((size_t)MTOK * KVHID)];

// ---------------------------------------------------------------------------
// Common helpers
// ---------------------------------------------------------------------------
__device__ __forceinline__ uint32_t swz(uint32_t off) {
    return off ^ ((off >> 3) & 0x70);
}
__device__ __forceinline__ uint32_t smem_u32(const void* p) {
    return (uint32_t)__cvta_generic_to_shared(p);
}
__device__ __forceinline__ void cp16(uint32_t dst, const void* src) {
    asm volatile("cp.async.cg.shared.global [%0], [%1], 16;\n" :: "r"(dst), "l"(src));
}
__device__ __forceinline__ void cp_commit() { asm volatile("cp.async.commit_group;\n"); }
__device__ __forceinline__ void cp_wait0() { asm volatile("cp.async.wait_group 0;\n"); }
__device__ __forceinline__ void cp_wait1() { asm volatile("cp.async.wait_group 1;\n"); }
__device__ __forceinline__ void ldsm4(uint32_t r[4], uint32_t addr) {
    asm volatile("ldmatrix.sync.aligned.m8n8.x4.shared.b16 {%0,%1,%2,%3}, [%4];\n"
        : "=r"(r[0]), "=r"(r[1]), "=r"(r[2]), "=r"(r[3]) : "r"(addr));
}
__device__ __forceinline__ void ldsm4t(uint32_t r[4], uint32_t addr) {
    asm volatile("ldmatrix.sync.aligned.m8n8.x4.trans.shared.b16 {%0,%1,%2,%3}, [%4];\n"
        : "=r"(r[0]), "=r"(r[1]), "=r"(r[2]), "=r"(r[3]) : "r"(addr));
}
__device__ __forceinline__ void mma16816(float c[4], const uint32_t a[4],
                                         uint32_t b0, uint32_t b1) {
    asm volatile(
        "mma.sync.aligned.m16n8k16.row.col.f32.bf16.bf16.f32 "
        "{%0,%1,%2,%3}, {%4,%5,%6,%7}, {%8,%9}, {%0,%1,%2,%3};\n"
        : "+f"(c[0]), "+f"(c[1]), "+f"(c[2]), "+f"(c[3])
        : "r"(a[0]), "r"(a[1]), "r"(a[2]), "r"(a[3]), "r"(b0), "r"(b1));
}
__device__ __forceinline__ void split2(float a, float b,
                                       __nv_bfloat162& h, __nv_bfloat162& l) {
    h = __floats2bfloat162_rn(a, b);
    l = __floats2bfloat162_rn(a - __bfloat162float(h.x), b - __bfloat162float(h.y));
}

// ---------------------------------------------------------------------------
// Fused split: one launch splits X, Wq, Wk, Wv, Wo (disjoint flat ranges).
// Region boundaries in float4 units.
// ---------------------------------------------------------------------------
#define S_X4 (MTOK * HID / 4)        // 4194304
#define S_W4 (HID * HID / 4)         // 4194304
#define S_K4 (KVHID * HID / 4)       // 1048576
#define S_B0 (S_X4)                  // end X
#define S_B1 (S_B0 + S_W4)           // end Wq
#define S_B2 (S_B1 + S_K4)           // end Wk
#define S_B3 (S_B2 + S_K4)           // end Wv
#define S_B4 (S_B3 + S_W4)           // end Wo (= total 14680064)

__global__ __launch_bounds__(256) void split_all_kernel(
    const float* __restrict__ X,  __nv_bfloat16* __restrict__ Xhi,  __nv_bfloat16* __restrict__ Xlo,
    const float* __restrict__ Wq, __nv_bfloat16* __restrict__ Wqhi, __nv_bfloat16* __restrict__ Wqlo,
    const float* __restrict__ Wk, __nv_bfloat16* __restrict__ Wkhi, __nv_bfloat16* __restrict__ Wklo,
    const float* __restrict__ Wv, __nv_bfloat16* __restrict__ Wvhi, __nv_bfloat16* __restrict__ Wvlo,
    const float* __restrict__ Wo, __nv_bfloat16* __restrict__ Wohi, __nv_bfloat16* __restrict__ Wolo)
{
    int gi = blockIdx.x * blockDim.x + threadIdx.x;
    const float* src;
    __nv_bfloat16 *hi, *lo;
    int i;
    if (gi < S_B0)      { src = X;  hi = Xhi;  lo = Xlo;  i = gi; }
    else if (gi < S_B1) { src = Wq; hi = Wqhi; lo = Wqlo; i = gi - S_B0; }
    else if (gi < S_B2) { src = Wk; hi = Wkhi; lo = Wklo; i = gi - S_B1; }
    else if (gi < S_B3) { src = Wv; hi = Wvhi; lo = Wvlo; i = gi - S_B2; }
    else                { src = Wo; hi = Wohi; lo = Wolo; i = gi - S_B3; }

    float4 v = ((const float4*)src)[i];
    __nv_bfloat162 H01, H23, L01, L23;
    split2(v.x, v.y, H01, L01);
    split2(v.z, v.w, H23, L23);
    ((__nv_bfloat162*)hi)[2 * i]     = H01;
    ((__nv_bfloat162*)hi)[2 * i + 1] = H23;
    ((__nv_bfloat162*)lo)[2 * i]     = L01;
    ((__nv_bfloat162*)lo)[2 * i + 1] = L23;
}

// ---------------------------------------------------------------------------
// bf16x3 mma.sync GEMM body (R14-verified config): C tile 128x128.
// 8 warps (wm {0,1}, wn {0..3}), warp tile 64x32, BK=64 bf16,
// 3-stage cp.async (16KB A + 16KB B per stage = 96KB total -> 2 CTAs/SM).
// Virtual K' = 3K: pass 0 = Ahi*Bhi, pass 1 = Ahi*Blo, pass 2 = Alo*Bhi.
// ---------------------------------------------------------------------------
#define G_STAGES 3
#define G_TILE   (128 * 64 * 2)               // 16KB per operand tile
#define G_SMEM   (G_STAGES * 2 * G_TILE)      // 96KB
#define G_KCHUNKS (3 * GK / 64)               // 192

__device__ __forceinline__ void gemm_body_128x128(
    const __nv_bfloat16* __restrict__ Ahi, const __nv_bfloat16* __restrict__ Alo,
    const __nv_bfloat16* __restrict__ Bhi, const __nv_bfloat16* __restrict__ Blo,
    float* __restrict__ Cf, __nv_bfloat16* __restrict__ Chi,
    __nv_bfloat16* __restrict__ Clo,
    int ldC, int bm, int bn, char* dsm)
{
    const uint32_t aS = smem_u32(dsm);
    const uint32_t bS = aS + G_STAGES * G_TILE;

    const int tid  = threadIdx.x;
    const int lane = tid & 31;
    const int wid  = tid >> 5;
    const int wm   = wid >> 2;
    const int wn   = wid & 3;

    float acc[4][4][4];
#pragma unroll
    for (int i = 0; i < 4; i++)
#pragma unroll
        for (int j = 0; j < 4; j++)
#pragma unroll
            for (int t = 0; t < 4; t++) acc[i][j][t] = 0.f;

    int lr[4], lj[4];
#pragma unroll
    for (int i = 0; i < 4; i++) {
        int lin = i * 256 + tid;
        lr[i] = lin >> 3;
        lj[i] = lin & 7;
    }

    auto issue_loads = [&](int c, int st) {
        int pass  = c >> 6;
        int kreal = (c & 63) << 6;
        const __nv_bfloat16* Asrc = (pass < 2) ? Ahi : Alo;
        const __nv_bfloat16* Bsrc = (pass == 1) ? Blo : Bhi;
#pragma unroll
        for (int i = 0; i < 4; i++) {
            uint32_t off = swz(lr[i] * 128 + lj[i] * 16);
            cp16(aS + st * G_TILE + off,
                 Asrc + (size_t)(bm + lr[i]) * GK + kreal + lj[i] * 8);
            cp16(bS + st * G_TILE + off,
                 Bsrc + (size_t)(bn + lr[i]) * GK + kreal + lj[i] * 8);
        }
    };

    issue_loads(0, 0); cp_commit();
    issue_loads(1, 1); cp_commit();

    for (int c = 0; c < G_KCHUNKS; c++) {
        cp_wait1();
        __syncthreads();

        if (c + 2 < G_KCHUNKS) issue_loads(c + 2, (c + 2) % G_STAGES);
        cp_commit();

        const int st = c % G_STAGES;
        const uint32_t aT = aS + st * G_TILE;
        const uint32_t bT = bS + st * G_TILE;

#pragma unroll
        for (int kk = 0; kk < 64; kk += 16) {
            uint32_t afr[4][4];
            uint32_t bfr[2][4];
#pragma unroll
            for (int mt = 0; mt < 4; mt++) {
                int row = wm * 64 + mt * 16 + (lane & 15);
                uint32_t off = row * 128 + kk * 2 + (lane >> 4) * 16;
                ldsm4(afr[mt], aT + swz(off));
            }
#pragma unroll
            for (int nt2 = 0; nt2 < 2; nt2++) {
                int row = wn * 32 + nt2 * 16 + (lane & 7) + ((lane >> 4) & 1) * 8;
                uint32_t off = row * 128 + kk * 2 + ((lane >> 3) & 1) * 16;
                ldsm4(bfr[nt2], bT + swz(off));
            }
#pragma unroll
            for (int mt = 0; mt < 4; mt++)
#pragma unroll
                for (int nt = 0; nt < 4; nt++)
                    mma16816(acc[mt][nt], afr[mt],
                             bfr[nt >> 1][(nt & 1) * 2],
                             bfr[nt >> 1][(nt & 1) * 2 + 1]);
        }
    }

    // epilogue: fp32 or bf16 hi/lo split
#pragma unroll
    for (int mt = 0; mt < 4; mt++) {
#pragma unroll
        for (int nt = 0; nt < 4; nt++) {
            int row = bm + wm * 64 + mt * 16 + (lane >> 2);
            int col = bn + wn * 32 + nt * 8 + (lane & 3) * 2;
            if (Cf) {
                *(float2*)&Cf[(size_t)row * ldC + col] =
                    make_float2(acc[mt][nt][0], acc[mt][nt][1]);
                *(float2*)&Cf[(size_t)(row + 8) * ldC + col] =
                    make_float2(acc[mt][nt][2], acc[mt][nt][3]);
            } else {
                __nv_bfloat162 h0, l0, h1, l1;
                split2(acc[mt][nt][0], acc[mt][nt][1], h0, l0);
                split2(acc[mt][nt][2], acc[mt][nt][3], h1, l1);
                *(__nv_bfloat162*)&Chi[(size_t)row * ldC + col] = h0;
                *(__nv_bfloat162*)&Clo[(size_t)row * ldC + col] = l0;
                *(__nv_bfloat162*)&Chi[(size_t)(row + 8) * ldC + col] = h1;
                *(__nv_bfloat162*)&Clo[(size_t)(row + 8) * ldC + col] = l1;
            }
        }
    }
}

// Fused QKV projection: virtual N = 6144 (Wq 4096 | Wk 1024 | Wv 1024).
__global__ __launch_bounds__(256) void gemm_qkv(
    const __nv_bfloat16* __restrict__ Xhi, const __nv_bfloat16* __restrict__ Xlo,
    const __nv_bfloat16* __restrict__ Wqhi, const __nv_bfloat16* __restrict__ Wqlo,
    const __nv_bfloat16* __restrict__ Wkhi, const __nv_bfloat16* __restrict__ Wklo,
    const __nv_bfloat16* __restrict__ Wvhi, const __nv_bfloat16* __restrict__ Wvlo,
    float* __restrict__ q, float* __restrict__ k,
    __nv_bfloat16* __restrict__ vhi, __nv_bfloat16* __restrict__ vlo)
{
    extern __shared__ __align__(16) char dsm[];
    const int bm = blockIdx.y * 128;
    const int bnG = blockIdx.x * 128;

    if (bnG < HID) {
        gemm_body_128x128(Xhi, Xlo, Wqhi, Wqlo, q, nullptr, nullptr,
                          HID, bm, bnG, dsm);
    } else if (bnG < HID + KVHID) {
        gemm_body_128x128(Xhi, Xlo, Wkhi, Wklo, k, nullptr, nullptr,
                          KVHID, bm, bnG - HID, dsm);
    } else {
        gemm_body_128x128(Xhi, Xlo, Wvhi, Wvlo, nullptr, vhi, vlo,
                          KVHID, bm, bnG - HID - KVHID, dsm);
    }
}

// O projection: bf16x3 inputs -> fp32 out
__global__ __launch_bounds__(256) void gemm_nt(
    const __nv_bfloat16* __restrict__ Ahi, const __nv_bfloat16* __restrict__ Alo,
    const __nv_bfloat16* __restrict__ Bhi, const __nv_bfloat16* __restrict__ Blo,
    float* __restrict__ C, int N)
{
    extern __shared__ __align__(16) char dsm[];
    gemm_body_128x128(Ahi, Alo, Bhi, Blo, C, nullptr, nullptr,
                      N, blockIdx.y * 128, blockIdx.x * 128, dsm);
}

// ---------------------------------------------------------------------------
// RoPE + split: q (scaled by 1/sqrt(d)) and k -> bf16 hi/lo pairs.
// ---------------------------------------------------------------------------
__global__ __launch_bounds__(256) void rope_split_kernel(
    const float* __restrict__ Qb, const float* __restrict__ Kb,
    __nv_bfloat16* __restrict__ qhi, __nv_bfloat16* __restrict__ qlo,
    __nv_bfloat16* __restrict__ khi, __nv_bfloat16* __restrict__ klo,
    const int* __restrict__ pos)
{
    int idx = blockIdx.x * blockDim.x + threadIdx.x;   // MTOK*64
    int token = idx >> 6;
    int j = idx & 63;
    double inv = exp(((double)(-2 * j) / 128.0) * log(10000.0));
    double ang = (double)pos[token] * inv;
    float c = (float)cos(ang);
    float s = (float)sin(ang);
    const float scale = 0.08838834764831845f;

    auto wr = [](__nv_bfloat16* hi, __nv_bfloat16* lo, size_t off, float y) {
        __nv_bfloat16 h = __float2bfloat16(y);
        hi[off] = h;
        lo[off] = __float2bfloat16(y - __bfloat162float(h));
    };

    const float* q = Qb + (size_t)token * HID;
    size_t qo = (size_t)token * HID;
#pragma unroll
    for (int h = 0; h < NHEADS; h++) {
        float x1 = q[h * HDIM + j];
        float x2 = q[h * HDIM + 64 + j];
        wr(qhi, qlo, qo + h * HDIM + j,      (x1 * c - x2 * s) * scale);
        wr(qhi, qlo, qo + h * HDIM + 64 + j, (x2 * c + x1 * s) * scale);
    }
    const float* k = Kb + (size_t)token * KVHID;
    size_t ko = (size_t)token * KVHID;
#pragma unroll
    for (int h = 0; h < NKV; h++) {
        float x1 = k[h * HDIM + j];
        float x2 = k[h * HDIM + 64 + j];
        wr(khi, klo, ko + h * HDIM + j,      x1 * c - x2 * s);
        wr(khi, klo, ko + h * HDIM + 64 + j, x2 * c + x1 * s);
    }
}

// ---------------------------------------------------------------------------
// Tensor-core flash attention (R14-verified: pass-merged fragment reuse,
// qt reversed, bf16 split epilogue). UNCHANGED from R14.
// ---------------------------------------------------------------------------
#define FQ  128
#define FKV 64
#define FLASH_SMEM (192 * 1024)

__global__ __launch_bounds__(256, 1) void flash_mma(
    const __nv_bfloat16* __restrict__ Qhi, const __nv_bfloat16* __restrict__ Qlo,
    const __nv_bfloat16* __restrict__ Khi, const __nv_bfloat16* __restrict__ Klo,
    const __nv_bfloat16* __restrict__ Vhi, const __nv_bfloat16* __restrict__ Vlo,
    __nv_bfloat16* __restrict__ Ohi, __nv_bfloat16* __restrict__ Olo)
{
    extern __shared__ __align__(16) char fsm[];
    const uint32_t smBase = smem_u32(fsm);

    const int tid = threadIdx.x, lane = tid & 31, wid = tid >> 5;
    const int qt = gridDim.x - 1 - blockIdx.x;   // heavy q-tiles first
    const int h = blockIdx.y, b = blockIdx.z;
    const int q0 = qt * FQ;
    const int kvh = h >> 2;
    const int ntiles = (q0 + FQ) / FKV;
    const int rowbase = wid * 16;

    {
        const __nv_bfloat16* qs[2] = {
            Qhi + ((size_t)b * SEQ + q0) * HID + h * HDIM,
            Qlo + ((size_t)b * SEQ + q0) * HID + h * HDIM };
#pragma unroll
        for (int t = 0; t < 2; t++)
#pragma unroll
            for (int i = 0; i < 8; i++) {
                int u = tid + 256 * i;
                int row = u >> 4, j = u & 15;
                cp16(smBase + t * 32768 + (j >> 3) * 16384 + swz(row * 128 + (j & 7) * 16),
                     qs[t] + (size_t)row * HID + j * 8);
            }
        cp_commit();
    }

    auto issue_kv = [&](int kt, int s) {
        const int k0 = kt * FKV;
        const size_t base = ((size_t)b * SEQ + k0) * KVHID + kvh * HDIM;
        const __nv_bfloat16* srcs[4] = { Khi + base, Klo + base, Vhi + base, Vlo + base };
        const uint32_t dbase = smBase + 65536 + s * 65536;
#pragma unroll
        for (int bfi = 0; bfi < 4; bfi++)
#pragma unroll
            for (int i = 0; i < 4; i++) {
                int u = tid + 256 * i;
                int row = u >> 4, j = u & 15;
                cp16(dbase + bfi * 16384 + (j >> 3) * 8192 + swz(row * 128 + (j & 7) * 16),
                     srcs[bfi] + (size_t)row * KVHID + j * 8);
            }
    };

    issue_kv(0, 0); cp_commit();

    float m0 = -1e30f, m1 = -1e30f, l0 = 0.f, l1 = 0.f;
    float oacc[16][4];
#pragma unroll
    for (int i = 0; i < 16; i++)
#pragma unroll
        for (int j = 0; j < 4; j++) oacc[i][j] = 0.f;

    for (int kt = 0; kt < ntiles; kt++) {
        if (kt + 1 < ntiles) { issue_kv(kt + 1, (kt + 1) & 1); cp_commit(); cp_wait1(); }
        else                 { cp_wait0(); }
        __syncthreads();

        const int k0 = kt * FKV;
        const bool active = (k0 <= q0 + rowbase + 15);
        if (active) {
            const uint32_t kvb = smBase + 65536 + (kt & 1) * 65536;
            const uint32_t khiS = kvb, kloS = kvb + 16384;
            const uint32_t vhiS = kvb + 32768, vloS = kvb + 49152;

            float sacc[8][4];
#pragma unroll
            for (int i = 0; i < 8; i++)
#pragma unroll
                for (int j = 0; j < 4; j++) sacc[i][j] = 0.f;

            // ---- S = QK^T, pass-merged ----
#pragma unroll
            for (int kk = 0; kk < 128; kk += 16) {
                uint32_t afh[4], afl[4];
                {
                    int row = rowbase + (lane & 15);
                    uint32_t off = (kk >> 6) * 16384 +
                        swz(row * 128 + (kk & 63) * 2 + (lane >> 4) * 16);
                    ldsm4(afh, smBase + off);            // Qhi
                    ldsm4(afl, smBase + 32768 + off);    // Qlo
                }
                uint32_t bf[4][4];
                uint32_t boff[4];
#pragma unroll
                for (int nt2 = 0; nt2 < 4; nt2++) {
                    int row = nt2 * 16 + (lane & 7) + ((lane >> 4) & 1) * 8;
                    boff[nt2] = (kk >> 6) * 8192 +
                        swz(row * 128 + (kk & 63) * 2 + ((lane >> 3) & 1) * 16);
                    ldsm4(bf[nt2], khiS + boff[nt2]);    // khi
                }
#pragma unroll
                for (int nt = 0; nt < 8; nt++)           // qhi*khi
                    mma16816(sacc[nt], afh,
                             bf[nt >> 1][(nt & 1) * 2],
                             bf[nt >> 1][(nt & 1) * 2 + 1]);
#pragma unroll
                for (int nt = 0; nt < 8; nt++)           // qlo*khi
                    mma16816(sacc[nt], afl,
                             bf[nt >> 1][(nt & 1) * 2],
                             bf[nt >> 1][(nt & 1) * 2 + 1]);
#pragma unroll
                for (int nt2 = 0; nt2 < 4; nt2++)
                    ldsm4(bf[nt2], kloS + boff[nt2]);    // klo
#pragma unroll
                for (int nt = 0; nt < 8; nt++)           // qhi*klo
                    mma16816(sacc[nt], afh,
                             bf[nt >> 1][(nt & 1) * 2],
                             bf[nt >> 1][(nt & 1) * 2 + 1]);
            }

            const int rg0 = q0 + rowbase + (lane >> 2);
            if (k0 + 63 > q0 + rowbase) {
#pragma unroll
                for (int nt = 0; nt < 8; nt++) {
                    int cbase = k0 + nt * 8 + (lane & 3) * 2;
                    if (cbase     > rg0)     sacc[nt][0] = -1e30f;
                    if (cbase + 1 > rg0)     sacc[nt][1] = -1e30f;
                    if (cbase     > rg0 + 8) sacc[nt][2] = -1e30f;
                    if (cbase + 1 > rg0 + 8) sacc[nt][3] = -1e30f;
                }
            }

            float mx0 = m0, mx1 = m1;
#pragma unroll
            for (int nt = 0; nt < 8; nt++) {
                mx0 = fmaxf(mx0, fmaxf(sacc[nt][0], sacc[nt][1]));
                mx1 = fmaxf(mx1, fmaxf(sacc[nt][2], sacc[nt][3]));
            }
            mx0 = fmaxf(mx0, __shfl_xor_sync(0xffffffff, mx0, 1));
            mx0 = fmaxf(mx0, __shfl_xor_sync(0xffffffff, mx0, 2));
            mx1 = fmaxf(mx1, __shfl_xor_sync(0xffffffff, mx1, 1));
            mx1 = fmaxf(mx1, __shfl_xor_sync(0xffffffff, mx1, 2));

            const float f0 = exp2f((m0 - mx0) * LOG2E);
            const float f1 = exp2f((m1 - mx1) * LOG2E);
            m0 = mx0; m1 = mx1;

            uint32_t pahi[4][4], palo[4][4];
            float l0a = 0.f, l1a = 0.f;
#pragma unroll
            for (int nt = 0; nt < 8; nt++) {
                float p0 = exp2f((sacc[nt][0] - mx0) * LOG2E);
                float p1 = exp2f((sacc[nt][1] - mx0) * LOG2E);
                float p2 = exp2f((sacc[nt][2] - mx1) * LOG2E);
                float p3 = exp2f((sacc[nt][3] - mx1) * LOG2E);
                l0a += p0 + p1; l1a += p2 + p3;
                int kt2 = nt >> 1, odd = nt & 1;
                __nv_bfloat162 h01, lo01, h23, lo23;
                split2(p0, p1, h01, lo01);
                split2(p2, p3, h23, lo23);
                pahi[kt2][odd * 2]     = *(uint32_t*)&h01;
                pahi[kt2][odd * 2 + 1] = *(uint32_t*)&h23;
                palo[kt2][odd * 2]     = *(uint32_t*)&lo01;
                palo[kt2][odd * 2 + 1] = *(uint32_t*)&lo23;
            }
            l0a += __shfl_xor_sync(0xffffffff, l0a, 1);
            l0a += __shfl_xor_sync(0xffffffff, l0a, 2);
            l1a += __shfl_xor_sync(0xffffffff, l1a, 1);
            l1a += __shfl_xor_sync(0xffffffff, l1a, 2);
            l0 = l0 * f0 + l0a;
            l1 = l1 * f1 + l1a;

#pragma unroll
            for (int nt = 0; nt < 16; nt++) {
                oacc[nt][0] *= f0; oacc[nt][1] *= f0;
                oacc[nt][2] *= f1; oacc[nt][3] *= f1;
            }

            // ---- O += P V, pass-merged ----
#pragma unroll
            for (int kt2 = 0; kt2 < 4; kt2++) {
#pragma unroll
                for (int nt16 = 0; nt16 < 8; nt16++) {
                    uint32_t vf[4];
                    int kv = kt2 * 16 + (lane & 15);
                    int d  = nt16 * 16 + (lane >> 4) * 8;
                    uint32_t off = (d >> 6) * 8192 + swz(kv * 128 + (d & 63) * 2);
                    ldsm4t(vf, vhiS + off);              // vhi
                    mma16816(oacc[nt16 * 2],     pahi[kt2], vf[0], vf[1]);
                    mma16816(oacc[nt16 * 2 + 1], pahi[kt2], vf[2], vf[3]);
                    mma16816(oacc[nt16 * 2],     palo[kt2], vf[0], vf[1]);
                    mma16816(oacc[nt16 * 2 + 1], palo[kt2], vf[2], vf[3]);
                    ldsm4t(vf, vloS + off);              // vlo
                    mma16816(oacc[nt16 * 2],     pahi[kt2], vf[0], vf[1]);
                    mma16816(oacc[nt16 * 2 + 1], pahi[kt2], vf[2], vf[3]);
                }
            }
        }
        __syncthreads();
    }

    // epilogue: normalize + bf16 hi/lo split store
    const float il0 = 1.f / l0, il1 = 1.f / l1;
    const size_t obase = ((size_t)b * SEQ + q0 + rowbase + (lane >> 2)) * HID + h * HDIM;
#pragma unroll
    for (int nt = 0; nt < 16; nt++) {
        int d = nt * 8 + (lane & 3) * 2;
        __nv_bfloat162 h0, lo0, h1, lo1;
        split2(oacc[nt][0] * il0, oacc[nt][1] * il0, h0, lo0);
        split2(oacc[nt][2] * il1, oacc[nt][3] * il1, h1, lo1);
        *(__nv_bfloat162*)&Ohi[obase + d]           = h0;
        *(__nv_bfloat162*)&Olo[obase + d]           = lo0;
        *(__nv_bfloat162*)&Ohi[obase + 8 * HID + d] = h1;
        *(__nv_bfloat162*)&Olo[obase + 8 * HID + d] = lo1;
    }
}

// ---------------------------------------------------------------------------
// Launch
// ---------------------------------------------------------------------------
extern "C" void kernel_launch(void* const* d_in, const int* in_sizes, int n_in,
                              void* d_out, int out_size)
{
    const float* X   = (const float*)d_in[0];
    const int*   pos = (const int*)d_in[1];
    const float* Wq  = (const float*)d_in[2];
    const float* Wk  = (const float*)d_in[3];
    const float* Wv  = (const float*)d_in[4];
    const float* Wo  = (const float*)d_in[5];
    float* out = (float*)d_out;

    float *q, *k;
    cudaGetSymbolAddress((void**)&q, g_q);
    cudaGetSymbolAddress((void**)&k, g_k);

    __nv_bfloat16 *Xhi, *Xlo, *Wqhi, *Wqlo, *Wkhi, *Wklo, *Wvhi, *Wvlo, *Wohi, *Wolo, *Ahi, *Alo;
    __nv_bfloat16 *qhi, *qlo, *khi, *klo, *vhi, *vlo;
    cudaGetSymbolAddress((void**)&Xhi,  g_Xhi);  cudaGetSymbolAddress((void**)&Xlo,  g_Xlo);
    cudaGetSymbolAddress((void**)&Wqhi, g_Wqhi); cudaGetSymbolAddress((void**)&Wqlo, g_Wqlo);
    cudaGetSymbolAddress((void**)&Wkhi, g_Wkhi); cudaGetSymbolAddress((void**)&Wklo, g_Wklo);
    cudaGetSymbolAddress((void**)&Wvhi, g_Wvhi); cudaGetSymbolAddress((void**)&Wvlo, g_Wvlo);
    cudaGetSymbolAddress((void**)&Wohi, g_Wohi); cudaGetSymbolAddress((void**)&Wolo, g_Wolo);
    cudaGetSymbolAddress((void**)&Ahi,  g_Ahi);  cudaGetSymbolAddress((void**)&Alo,  g_Alo);
    cudaGetSymbolAddress((void**)&qhi,  g_qhi);  cudaGetSymbolAddress((void**)&qlo,  g_qlo);
    cudaGetSymbolAddress((void**)&khi,  g_khi);  cudaGetSymbolAddress((void**)&klo,  g_klo);
    cudaGetSymbolAddress((void**)&vhi,  g_vhi);  cudaGetSymbolAddress((void**)&vlo,  g_vlo);

    // Fused split of all five fp32 inputs (X, Wq, Wk, Wv, Wo)
    split_all_kernel<<<S_B4 / 256, 256>>>(
        X, Xhi, Xlo, Wq, Wqhi, Wqlo, Wk, Wkhi, Wklo,
        Wv, Wvhi, Wvlo, Wo, Wohi, Wolo);

    // Fused QKV projection (virtual N = 6144; V epilogue writes bf16 split)
    cudaFuncSetAttribute(gemm_qkv, cudaFuncAttributeMaxDynamicSharedMemorySize, G_SMEM);
    cudaFuncSetAttribute(gemm_nt,  cudaFuncAttributeMaxDynamicSharedMemorySize, G_SMEM);
    gemm_qkv<<<dim3((HID + 2 * KVHID) / 128, MTOK / 128), 256, G_SMEM>>>(
        Xhi, Xlo, Wqhi, Wqlo, Wkhi, Wklo, Wvhi, Wvlo, q, k, vhi, vlo);

    // RoPE (+scale) and split for flash operands
    rope_split_kernel<<<(MTOK * 64) / 256, 256>>>(q, k, qhi, qlo, khi, klo, pos);

    // Tensor-core flash attention (epilogue writes bf16 split directly)
    cudaFuncSetAttribute(flash_mma, cudaFuncAttributeMaxDynamicSharedMemorySize, FLASH_SMEM);
    flash_mma<<<dim3(SEQ / FQ, NHEADS, BATCH), 256, FLASH_SMEM>>>(
        qhi, qlo, khi, klo, vhi, vlo, Ahi, Alo);

    // Output projection
    gemm_nt<<<dim3(HID / 128, MTOK / 128), 256, G_SMEM>>>(Ahi, Alo, Wohi, Wolo, out, HID);
}